// round 1
// baseline (speedup 1.0000x reference)
#include <cuda_runtime.h>
#include <cstdint>
#include <math.h>

#define HWSZ 262144   // 512*512
#define HDIM 512
#define WDIM 512
#define CDIM 64

// Scratch: interleaved (b, hw, 192ch) layout. 2*262144*192 floats = ~402 MB.
__device__ float g_scratch[2ull * HWSZ * 192];
__device__ float g_Wc[192 * 64];
__device__ float g_bc[64];
__device__ int   g_coord64;

__device__ __forceinline__ float gelu_exact(float x) {
    return 0.5f * x * (1.0f + erff(x * 0.70710678118654752f));
}

// ---------------------------------------------------------------------------
// Setup: fold w_lin/w1 into combined Wc[192,64], bc[64]; detect coord dtype.
// ---------------------------------------------------------------------------
__global__ void setup_kernel(const float* __restrict__ w_lin,
                             const float* __restrict__ b_lin,
                             const float* __restrict__ w1,
                             const float* __restrict__ b1,
                             const void*  lidar_raw)
{
    int idx = blockIdx.x * blockDim.x + threadIdx.x;
    if (idx == 0) {
        // int64 coords (<512, >=0) have all-zero high words. int32 coords
        // make 32 consecutive odd words all-zero with prob 512^-32.
        const int* w = (const int*)lidar_raw;
        int all0 = 1;
        for (int i = 0; i < 32; i++) all0 &= (w[2 * i + 1] == 0);
        g_coord64 = all0;
    }
    if (idx < 128 * 64) {
        // Wc[k][j] = sum_m w_lin[k][m] * w1[m][j],  k in [0,128)
        int k = idx >> 6, j = idx & 63;
        float s = 0.f;
        for (int m = 0; m < 64; m++) s = fmaf(w_lin[k * 64 + m], w1[m * 64 + j], s);
        g_Wc[idx] = s;
    } else if (idx < 192 * 64) {
        // Wc rows 128..191 = w1 rows 64..127 (flow part)
        int t = idx - 128 * 64;
        int k2 = t >> 6, j = t & 63;
        g_Wc[idx] = w1[(64 + k2) * 64 + j];
    } else if (idx < 192 * 64 + 64) {
        int j = idx - 192 * 64;
        float s = b1[j];
        for (int m = 0; m < 64; m++) s = fmaf(b_lin[m], w1[m * 64 + j], s);
        g_bc[j] = s;
    }
}

// ---------------------------------------------------------------------------
// Transpose (B,C,H,W) x3 maps -> scratch[b][hw][m*64+ch]
// ---------------------------------------------------------------------------
__global__ void transpose_kernel(const float* __restrict__ p0,
                                 const float* __restrict__ p1,
                                 const float* __restrict__ fl)
{
    __shared__ float T[64][65];
    int b = blockIdx.y;
    size_t hw0 = (size_t)blockIdx.x * 64;
    const float* maps[3] = {p0, p1, fl};
#pragma unroll
    for (int m = 0; m < 3; m++) {
        const float* src = maps[m] + (size_t)b * CDIM * HWSZ;
        for (int i = threadIdx.x; i < 4096; i += 256) {
            int c = i >> 6, x = i & 63;
            T[c][x] = src[(size_t)c * HWSZ + hw0 + x];   // coalesced 128B/warp
        }
        __syncthreads();
        float* dst = g_scratch + ((size_t)b * HWSZ + hw0) * 192 + m * 64;
        for (int i = threadIdx.x; i < 4096; i += 256) {
            int y = i >> 6, ch = i & 63;
            dst[(size_t)y * 192 + ch] = T[ch][y];        // coalesced, conflict-free
        }
        __syncthreads();
    }
}

// ---------------------------------------------------------------------------
// Fused gather + MLP. 64 points per block, 256 threads, 4x4 register tiles.
// ---------------------------------------------------------------------------
__global__ __launch_bounds__(256, 2)
void mlp_kernel(const void* __restrict__ lc_raw, const void* __restrict__ rc_raw,
                const float* __restrict__ w2, const float* __restrict__ b2,
                const float* __restrict__ w3, const float* __restrict__ b3,
                const float* __restrict__ w4, const float* __restrict__ b4,
                float* __restrict__ out, int Nl, int Nr)
{
    extern __shared__ float sm[];
    float* Xs  = sm;                // [192][68]  k-major, point minor (pad 68)
    float* Wcs = sm + 192 * 68;     // [192][64]
    float* w2s = Wcs + 192 * 64;    // [64][32]
    float* w3s = w2s + 64 * 32;     // [32][16]
    float* w4s = w3s + 32 * 16;     // [16]
    float* bcs = w4s + 16;          // [64]
    float* b2s = bcs + 64;          // [32]
    float* b3s = b2s + 32;          // [16]
    float* b4s = b3s + 16;          // [1]

    int tid = threadIdx.x;
    int b = blockIdx.y;
    int N = Nl + Nr;
    int pt0 = blockIdx.x * 64;

    for (int i = tid; i < 192 * 64; i += 256) Wcs[i] = g_Wc[i];
    for (int i = tid; i < 64 * 32; i += 256)  w2s[i] = w2[i];
    for (int i = tid; i < 32 * 16; i += 256)  w3s[i] = w3[i];
    if (tid < 16) w4s[tid] = w4[tid];
    if (tid < 64) bcs[tid] = g_bc[tid];
    if (tid < 32) b2s[tid] = b2[tid];
    if (tid < 16) b3s[tid] = b3[tid];
    if (tid == 0) b4s[0] = b4[0];

    int is64 = g_coord64;

    // ---- Gather: 4 threads per point, 768B contiguous per point ----
    {
        int p = tid >> 2;
        int lane2 = tid & 3;
        int pt = pt0 + p;
        const float* rowptr = nullptr;
        if (pt < N) {
            long long r, c;
            if (pt < Nl) {
                long long base = ((long long)b * Nl + pt) * 3;
                if (is64) { const long long* lc = (const long long*)lc_raw; r = lc[base + 1]; c = lc[base + 2]; }
                else      { const int*       lc = (const int*)lc_raw;       r = lc[base + 1]; c = lc[base + 2]; }
            } else {
                long long base = ((long long)b * Nr + (pt - Nl)) * 3;
                if (is64) { const long long* rc = (const long long*)rc_raw; r = rc[base + 1]; c = rc[base + 2]; }
                else      { const int*       rc = (const int*)rc_raw;       r = rc[base + 1]; c = rc[base + 2]; }
            }
            rowptr = g_scratch + 192ull * ((size_t)b * HWSZ + (size_t)r * WDIM + (size_t)c);
        }
#pragma unroll
        for (int i = 0; i < 12; i++) {
            int q = i * 4 + lane2;            // float4 index 0..47
            float4 v = make_float4(0.f, 0.f, 0.f, 0.f);
            if (rowptr) v = *(const float4*)(rowptr + q * 4);
            int k0 = 4 * q;
            Xs[(k0 + 0) * 68 + p] = v.x;
            Xs[(k0 + 1) * 68 + p] = v.y;
            Xs[(k0 + 2) * 68 + p] = v.z;
            Xs[(k0 + 3) * 68 + p] = v.w;
        }
    }
    __syncthreads();

    int pi4 = (tid & 15) * 4;   // 4 points per thread
    int ojg = tid >> 4;         // 0..15 output group

    // ---- Layer 1: 192 -> 64, gelu.  acc[p][o], 2 LDS.128 per 16 FMA ----
    {
        int oj4 = ojg * 4;
        float acc[4][4] = {};
#pragma unroll 4
        for (int k = 0; k < 192; k++) {
            float4 xv = *(const float4*)&Xs[k * 68 + pi4];
            float4 wv = *(const float4*)&Wcs[k * 64 + oj4];
            float xs[4] = {xv.x, xv.y, xv.z, xv.w};
            float ws[4] = {wv.x, wv.y, wv.z, wv.w};
#pragma unroll
            for (int p = 0; p < 4; p++)
#pragma unroll
                for (int o = 0; o < 4; o++) acc[p][o] = fmaf(xs[p], ws[o], acc[p][o]);
        }
        __syncthreads();   // all threads done reading Xs rows 0..191
#pragma unroll
        for (int o = 0; o < 4; o++) {
            float bb = bcs[oj4 + o];
#pragma unroll
            for (int p = 0; p < 4; p++)
                Xs[(oj4 + o) * 68 + pi4 + p] = gelu_exact(acc[p][o] + bb);  // H1 rows 0..63
        }
    }
    __syncthreads();

    // ---- Layer 2: 64 -> 32, gelu. writes rows 64..95 (disjoint from reads) ----
    {
        int oj2 = ojg * 2;
        float acc[4][2] = {};
#pragma unroll 4
        for (int k = 0; k < 64; k++) {
            float4 xv = *(const float4*)&Xs[k * 68 + pi4];
            float2 wv = *(const float2*)&w2s[k * 32 + oj2];
            float xs[4] = {xv.x, xv.y, xv.z, xv.w};
#pragma unroll
            for (int p = 0; p < 4; p++) {
                acc[p][0] = fmaf(xs[p], wv.x, acc[p][0]);
                acc[p][1] = fmaf(xs[p], wv.y, acc[p][1]);
            }
        }
#pragma unroll
        for (int o = 0; o < 2; o++) {
            float bb = b2s[oj2 + o];
#pragma unroll
            for (int p = 0; p < 4; p++)
                Xs[(64 + oj2 + o) * 68 + pi4 + p] = gelu_exact(acc[p][o] + bb);
        }
    }
    __syncthreads();

    // ---- Layer 3: 32 -> 16, gelu. reads rows 64..95, writes rows 96..111 ----
    {
        float acc[4] = {};
#pragma unroll 4
        for (int k = 0; k < 32; k++) {
            float4 xv = *(const float4*)&Xs[(64 + k) * 68 + pi4];
            float wv = w3s[k * 16 + ojg];
            acc[0] = fmaf(xv.x, wv, acc[0]);
            acc[1] = fmaf(xv.y, wv, acc[1]);
            acc[2] = fmaf(xv.z, wv, acc[2]);
            acc[3] = fmaf(xv.w, wv, acc[3]);
        }
        float bb = b3s[ojg];
#pragma unroll
        for (int p = 0; p < 4; p++)
            Xs[(96 + ojg) * 68 + pi4 + p] = gelu_exact(acc[p] + bb);
    }
    __syncthreads();

    // ---- Layer 4: 16 -> 1, sigmoid ----
    if (tid < 64) {
        int pt = pt0 + tid;
        if (pt < N) {
            float s = b4s[0];
#pragma unroll
            for (int k = 0; k < 16; k++) s = fmaf(Xs[(96 + k) * 68 + tid], w4s[k], s);
            out[(size_t)b * N + pt] = 1.f / (1.f + expf(-s));
        }
    }
}

// ---------------------------------------------------------------------------
extern "C" void kernel_launch(void* const* d_in, const int* in_sizes, int n_in,
                              void* d_out, int out_size)
{
    const float* p0    = (const float*)d_in[0];
    const float* p1    = (const float*)d_in[1];
    const float* fl    = (const float*)d_in[2];
    const void*  lc    = d_in[3];
    const void*  rc    = d_in[4];
    const float* w_lin = (const float*)d_in[5];
    const float* b_lin = (const float*)d_in[6];
    const float* w1    = (const float*)d_in[7];
    const float* b1    = (const float*)d_in[8];
    const float* w2    = (const float*)d_in[9];
    const float* b2    = (const float*)d_in[10];
    const float* w3    = (const float*)d_in[11];
    const float* b3    = (const float*)d_in[12];
    const float* w4    = (const float*)d_in[13];
    const float* b4    = (const float*)d_in[14];

    int B  = in_sizes[0] / (CDIM * HWSZ);   // = 2
    int Nl = in_sizes[3] / (B * 3);         // element counts are dtype-independent
    int Nr = in_sizes[4] / (B * 3);
    int N  = Nl + Nr;

    setup_kernel<<<49, 256>>>(w_lin, b_lin, w1, b1, lc);

    dim3 tg(HWSZ / 64, B);
    transpose_kernel<<<tg, 256>>>(p0, p1, fl);

    size_t smem = (size_t)(192 * 68 + 192 * 64 + 64 * 32 + 32 * 16 + 16 + 64 + 32 + 16 + 1) * sizeof(float);
    cudaFuncSetAttribute(mlp_kernel, cudaFuncAttributeMaxDynamicSharedMemorySize, (int)smem);
    dim3 mg((N + 63) / 64, B);
    mlp_kernel<<<mg, 256, smem>>>(lc, rc, w2, b2, w3, b3, w4, b4, (float*)d_out, Nl, Nr);
}

// round 2
// speedup vs baseline: 1.2743x; 1.2743x over previous
#include <cuda_runtime.h>
#include <cuda_fp16.h>
#include <cstdint>
#include <math.h>

#define HWSZ 262144   // 512*512
#define WDIM 512
#define CDIM 64

// Scratch: interleaved (b, hw, 192ch) fp16 layout. 2*262144*192*2B = ~192 MB.
__device__ __half g_scratch[2ull * HWSZ * 192];
__device__ float g_Wc[192 * 64];
__device__ float g_bc[64];
__device__ int   g_coord64;

__device__ __forceinline__ float gelu_exact(float x) {
    return 0.5f * x * (1.0f + erff(x * 0.70710678118654752f));
}

// packed fp32x2 helpers (FFMA2 — only reachable via PTX)
__device__ __forceinline__ unsigned long long pack2(float a, float b) {
    unsigned long long r;
    asm("mov.b64 %0, {%1, %2};" : "=l"(r) : "f"(a), "f"(b));
    return r;
}
__device__ __forceinline__ float2 unpack2(unsigned long long a) {
    float2 r;
    asm("mov.b64 {%0, %1}, %2;" : "=f"(r.x), "=f"(r.y) : "l"(a));
    return r;
}
__device__ __forceinline__ unsigned long long fma2(unsigned long long a,
                                                   unsigned long long b,
                                                   unsigned long long c) {
    unsigned long long d;
    asm("fma.rn.f32x2 %0, %1, %2, %3;" : "=l"(d) : "l"(a), "l"(b), "l"(c));
    return d;
}

// ---------------------------------------------------------------------------
// Setup: fold w_lin/w1 into combined Wc[192,64], bc[64]; detect coord dtype.
// ---------------------------------------------------------------------------
__global__ void setup_kernel(const float* __restrict__ w_lin,
                             const float* __restrict__ b_lin,
                             const float* __restrict__ w1,
                             const float* __restrict__ b1,
                             const void*  lidar_raw)
{
    int idx = blockIdx.x * blockDim.x + threadIdx.x;
    if (idx == 0) {
        const int* w = (const int*)lidar_raw;
        int all0 = 1;
        for (int i = 0; i < 32; i++) all0 &= (w[2 * i + 1] == 0);
        g_coord64 = all0;
    }
    if (idx < 128 * 64) {
        int k = idx >> 6, j = idx & 63;
        float s = 0.f;
        for (int m = 0; m < 64; m++) s = fmaf(w_lin[k * 64 + m], w1[m * 64 + j], s);
        g_Wc[idx] = s;
    } else if (idx < 192 * 64) {
        int t = idx - 128 * 64;
        int k2 = t >> 6, j = t & 63;
        g_Wc[idx] = w1[(64 + k2) * 64 + j];
    } else if (idx < 192 * 64 + 64) {
        int j = idx - 192 * 64;
        float s = b1[j];
        for (int m = 0; m < 64; m++) s = fmaf(b_lin[m], w1[m * 64 + j], s);
        g_bc[j] = s;
    }
}

// ---------------------------------------------------------------------------
// Transpose (B,C,H,W) x3 fp32 maps -> fp16 scratch[b][hw][m*64+ch]
// ---------------------------------------------------------------------------
__global__ void transpose_kernel(const float* __restrict__ p0,
                                 const float* __restrict__ p1,
                                 const float* __restrict__ fl)
{
    __shared__ float T[64][65];
    int b = blockIdx.y;
    size_t hw0 = (size_t)blockIdx.x * 64;
    const float* maps[3] = {p0, p1, fl};
#pragma unroll
    for (int m = 0; m < 3; m++) {
        const float* src = maps[m] + (size_t)b * CDIM * HWSZ;
        for (int i = threadIdx.x; i < 4096; i += 256) {
            int c = i >> 6, x = i & 63;
            T[c][x] = src[(size_t)c * HWSZ + hw0 + x];   // coalesced 128B/warp
        }
        __syncthreads();
        __half* dst = g_scratch + ((size_t)b * HWSZ + hw0) * 192 + m * 64;
        for (int i = threadIdx.x; i < 2048; i += 256) {
            int y = i >> 5, c2 = i & 31;                 // pixel, half2-channel
            float a0 = T[2 * c2][y], a1 = T[2 * c2 + 1][y];
            *(__half2*)(dst + (size_t)y * 192 + 2 * c2) = __floats2half2_rn(a0, a1);
        }
        __syncthreads();
    }
}

// ---------------------------------------------------------------------------
// Fused gather + MLP. 64 points/block, 256 threads, packed f32x2 FMA.
// ---------------------------------------------------------------------------
__global__ __launch_bounds__(256, 2)
void mlp_kernel(const void* __restrict__ lc_raw, const void* __restrict__ rc_raw,
                const float* __restrict__ w2, const float* __restrict__ b2,
                const float* __restrict__ w3, const float* __restrict__ b3,
                const float* __restrict__ w4, const float* __restrict__ b4,
                float* __restrict__ out, int Nl, int Nr)
{
    extern __shared__ float sm[];
    float* Xs  = sm;                // [192][68]  k-major, point minor (pad 68)
    float* Wcs = sm + 192 * 68;     // [192][64]
    float* w2s = Wcs + 192 * 64;    // [64][32]
    float* w3s = w2s + 64 * 32;     // [32][16]
    float* w4s = w3s + 32 * 16;     // [16]
    float* bcs = w4s + 16;          // [64]
    float* b2s = bcs + 64;          // [32]
    float* b3s = b2s + 32;          // [16]
    float* b4s = b3s + 16;          // [1]

    int tid = threadIdx.x;
    int b = blockIdx.y;
    int N = Nl + Nr;
    int pt0 = blockIdx.x * 64;

    for (int i = tid; i < 192 * 64; i += 256) Wcs[i] = g_Wc[i];
    for (int i = tid; i < 64 * 32; i += 256)  w2s[i] = w2[i];
    for (int i = tid; i < 32 * 16; i += 256)  w3s[i] = w3[i];
    if (tid < 16) w4s[tid] = w4[tid];
    if (tid < 64) bcs[tid] = g_bc[tid];
    if (tid < 32) b2s[tid] = b2[tid];
    if (tid < 16) b3s[tid] = b3[tid];
    if (tid == 0) b4s[0] = b4[0];

    int is64 = g_coord64;

    // ---- Gather: 4 threads per point, 384B (192 fp16) contiguous per point ----
    {
        int p = tid >> 2;
        int lane2 = tid & 3;
        int pt = pt0 + p;
        const __half* rowptr = nullptr;
        if (pt < N) {
            long long r, c;
            if (pt < Nl) {
                long long base = ((long long)b * Nl + pt) * 3;
                if (is64) { const long long* lc = (const long long*)lc_raw; r = lc[base + 1]; c = lc[base + 2]; }
                else      { const int*       lc = (const int*)lc_raw;       r = lc[base + 1]; c = lc[base + 2]; }
            } else {
                long long base = ((long long)b * Nr + (pt - Nl)) * 3;
                if (is64) { const long long* rc = (const long long*)rc_raw; r = rc[base + 1]; c = rc[base + 2]; }
                else      { const int*       rc = (const int*)rc_raw;       r = rc[base + 1]; c = rc[base + 2]; }
            }
            rowptr = g_scratch + 192ull * ((size_t)b * HWSZ + (size_t)r * WDIM + (size_t)c);
        }
#pragma unroll
        for (int i = 0; i < 6; i++) {
            int q = i * 4 + lane2;            // 16B chunk index 0..23 (8 halves each)
            uint4 v = make_uint4(0, 0, 0, 0);
            if (rowptr) v = *(const uint4*)(rowptr + q * 8);
            int k0 = q * 8;
            unsigned u[4] = {v.x, v.y, v.z, v.w};
#pragma unroll
            for (int j = 0; j < 4; j++) {
                float2 f = __half22float2(*(const __half2*)&u[j]);
                Xs[(k0 + 2 * j + 0) * 68 + p] = f.x;
                Xs[(k0 + 2 * j + 1) * 68 + p] = f.y;
            }
        }
    }
    __syncthreads();

    int pi4 = (tid & 15) * 4;   // 4 points per thread (two packed pairs)
    int ojg = tid >> 4;         // 0..15 output group

    // ---- Layer 1: 192 -> 64, gelu.  8 FFMA2 per k per thread ----
    {
        int oj4 = ojg * 4;
        unsigned long long acc[2][4] = {};
#pragma unroll 4
        for (int k = 0; k < 192; k++) {
            ulonglong2 xp = *(const ulonglong2*)&Xs[k * 68 + pi4];  // (p0,p1),(p2,p3)
            float4 wv = *(const float4*)&Wcs[k * 64 + oj4];
            unsigned long long wp[4] = {pack2(wv.x, wv.x), pack2(wv.y, wv.y),
                                        pack2(wv.z, wv.z), pack2(wv.w, wv.w)};
#pragma unroll
            for (int o = 0; o < 4; o++) {
                acc[0][o] = fma2(xp.x, wp[o], acc[0][o]);
                acc[1][o] = fma2(xp.y, wp[o], acc[1][o]);
            }
        }
        __syncthreads();   // all threads done reading Xs rows 0..191
#pragma unroll
        for (int o = 0; o < 4; o++) {
            float bb = bcs[oj4 + o];
            float2 lo = unpack2(acc[0][o]), hi = unpack2(acc[1][o]);
            Xs[(oj4 + o) * 68 + pi4 + 0] = gelu_exact(lo.x + bb);
            Xs[(oj4 + o) * 68 + pi4 + 1] = gelu_exact(lo.y + bb);
            Xs[(oj4 + o) * 68 + pi4 + 2] = gelu_exact(hi.x + bb);
            Xs[(oj4 + o) * 68 + pi4 + 3] = gelu_exact(hi.y + bb);
        }
    }
    __syncthreads();

    // ---- Layer 2: 64 -> 32, gelu. writes rows 64..95 (disjoint from reads) ----
    {
        int oj2 = ojg * 2;
        unsigned long long acc[2][2] = {};
#pragma unroll 4
        for (int k = 0; k < 64; k++) {
            ulonglong2 xp = *(const ulonglong2*)&Xs[k * 68 + pi4];
            float2 wv = *(const float2*)&w2s[k * 32 + oj2];
            unsigned long long w0 = pack2(wv.x, wv.x), w1p = pack2(wv.y, wv.y);
            acc[0][0] = fma2(xp.x, w0,  acc[0][0]);
            acc[1][0] = fma2(xp.y, w0,  acc[1][0]);
            acc[0][1] = fma2(xp.x, w1p, acc[0][1]);
            acc[1][1] = fma2(xp.y, w1p, acc[1][1]);
        }
#pragma unroll
        for (int o = 0; o < 2; o++) {
            float bb = b2s[oj2 + o];
            float2 lo = unpack2(acc[0][o]), hi = unpack2(acc[1][o]);
            Xs[(64 + oj2 + o) * 68 + pi4 + 0] = gelu_exact(lo.x + bb);
            Xs[(64 + oj2 + o) * 68 + pi4 + 1] = gelu_exact(lo.y + bb);
            Xs[(64 + oj2 + o) * 68 + pi4 + 2] = gelu_exact(hi.x + bb);
            Xs[(64 + oj2 + o) * 68 + pi4 + 3] = gelu_exact(hi.y + bb);
        }
    }
    __syncthreads();

    // ---- Layer 3: 32 -> 16, gelu. reads rows 64..95, writes rows 96..111 ----
    {
        unsigned long long a0 = 0, a1 = 0;
#pragma unroll 4
        for (int k = 0; k < 32; k++) {
            ulonglong2 xp = *(const ulonglong2*)&Xs[(64 + k) * 68 + pi4];
            float w = w3s[k * 16 + ojg];
            unsigned long long wp = pack2(w, w);
            a0 = fma2(xp.x, wp, a0);
            a1 = fma2(xp.y, wp, a1);
        }
        float bb = b3s[ojg];
        float2 lo = unpack2(a0), hi = unpack2(a1);
        Xs[(96 + ojg) * 68 + pi4 + 0] = gelu_exact(lo.x + bb);
        Xs[(96 + ojg) * 68 + pi4 + 1] = gelu_exact(lo.y + bb);
        Xs[(96 + ojg) * 68 + pi4 + 2] = gelu_exact(hi.x + bb);
        Xs[(96 + ojg) * 68 + pi4 + 3] = gelu_exact(hi.y + bb);
    }
    __syncthreads();

    // ---- Layer 4: 16 -> 1, sigmoid ----
    if (tid < 64) {
        int pt = pt0 + tid;
        if (pt < N) {
            float s = b4s[0];
#pragma unroll
            for (int k = 0; k < 16; k++) s = fmaf(Xs[(96 + k) * 68 + tid], w4s[k], s);
            out[(size_t)b * N + pt] = 1.f / (1.f + expf(-s));
        }
    }
}

// ---------------------------------------------------------------------------
extern "C" void kernel_launch(void* const* d_in, const int* in_sizes, int n_in,
                              void* d_out, int out_size)
{
    const float* p0    = (const float*)d_in[0];
    const float* p1    = (const float*)d_in[1];
    const float* fl    = (const float*)d_in[2];
    const void*  lc    = d_in[3];
    const void*  rc    = d_in[4];
    const float* w_lin = (const float*)d_in[5];
    const float* b_lin = (const float*)d_in[6];
    const float* w1    = (const float*)d_in[7];
    const float* b1    = (const float*)d_in[8];
    const float* w2    = (const float*)d_in[9];
    const float* b2    = (const float*)d_in[10];
    const float* w3    = (const float*)d_in[11];
    const float* b3    = (const float*)d_in[12];
    const float* w4    = (const float*)d_in[13];
    const float* b4    = (const float*)d_in[14];

    int B  = in_sizes[0] / (CDIM * HWSZ);   // = 2
    int Nl = in_sizes[3] / (B * 3);
    int Nr = in_sizes[4] / (B * 3);
    int N  = Nl + Nr;

    setup_kernel<<<49, 256>>>(w_lin, b_lin, w1, b1, lc);

    dim3 tg(HWSZ / 64, B);
    transpose_kernel<<<tg, 256>>>(p0, p1, fl);

    size_t smem = (size_t)(192 * 68 + 192 * 64 + 64 * 32 + 32 * 16 + 16 + 64 + 32 + 16 + 1) * sizeof(float);
    cudaFuncSetAttribute(mlp_kernel, cudaFuncAttributeMaxDynamicSharedMemorySize, (int)smem);
    dim3 mg((N + 63) / 64, B);
    mlp_kernel<<<mg, 256, smem>>>(lc, rc, w2, b2, w3, b3, w4, b4, (float*)d_out, Nl, Nr);
}

// round 5
// speedup vs baseline: 1.6841x; 1.3216x over previous
#include <cuda_runtime.h>
#include <cuda_bf16.h>
#include <cstdint>
#include <math.h>

#define HWSZ 262144   // 512*512
#define WDIM 512
#define CDIM 64

// Scratch: interleaved (b, hw, 192ch) bf16 layout. ~192 MB.
__device__ __nv_bfloat16 g_scratch[2ull * HWSZ * 192];
__device__ __nv_bfloat16 g_WcT[64 * 192];   // combined layer1 weight, [out j][k] (B col-major)
__device__ float g_bc[64];
__device__ float g_w2T[32 * 64];            // [j][k]
__device__ float g_w3T[16 * 32];            // [j][k]
__device__ int   g_coord64;

__device__ __forceinline__ float gelu_exact(float x) {
    return 0.5f * x * (1.0f + erff(x * 0.70710678118654752f));
}

// ---- packed fp32x2 helpers (FFMA2 only reachable via PTX) ----
__device__ __forceinline__ unsigned long long pack2(float a, float b) {
    unsigned long long r;
    asm("mov.b64 %0, {%1, %2};" : "=l"(r) : "f"(a), "f"(b));
    return r;
}
__device__ __forceinline__ float2 unpack2(unsigned long long a) {
    float2 r;
    asm("mov.b64 {%0, %1}, %2;" : "=f"(r.x), "=f"(r.y) : "l"(a));
    return r;
}
__device__ __forceinline__ unsigned long long fma2(unsigned long long a,
                                                   unsigned long long b,
                                                   unsigned long long c) {
    unsigned long long d;
    asm("fma.rn.f32x2 %0, %1, %2, %3;" : "=l"(d) : "l"(a), "l"(b), "l"(c));
    return d;
}

// ---- warp-MMA helpers (plain PTX ISA; compiles for compute_103) ----
__device__ __forceinline__ uint32_t smem_u32(const void* p) {
    uint32_t a;
    asm("{ .reg .u64 t; cvta.to.shared.u64 t, %1; cvt.u32.u64 %0, t; }" : "=r"(a) : "l"(p));
    return a;
}
__device__ __forceinline__ void ldsm4(uint32_t* r, uint32_t addr) {
    asm volatile("ldmatrix.sync.aligned.m8n8.x4.shared.b16 {%0,%1,%2,%3}, [%4];"
        : "=r"(r[0]), "=r"(r[1]), "=r"(r[2]), "=r"(r[3]) : "r"(addr));
}
__device__ __forceinline__ void ldsm2(uint32_t* r, uint32_t addr) {
    asm volatile("ldmatrix.sync.aligned.m8n8.x2.shared.b16 {%0,%1}, [%2];"
        : "=r"(r[0]), "=r"(r[1]) : "r"(addr));
}
__device__ __forceinline__ void mma16816(float* d, const uint32_t* a, const uint32_t* b) {
    asm volatile("mma.sync.aligned.m16n8k16.row.col.f32.bf16.bf16.f32 "
        "{%0,%1,%2,%3}, {%4,%5,%6,%7}, {%8,%9}, {%0,%1,%2,%3};"
        : "+f"(d[0]), "+f"(d[1]), "+f"(d[2]), "+f"(d[3])
        : "r"(a[0]), "r"(a[1]), "r"(a[2]), "r"(a[3]), "r"(b[0]), "r"(b[1]));
}

// SMEM layout (bytes). X rows padded to 400B; W rows padded to 400B.
#define XPITCH 400
#define HPITCH 272     // H1: 68 f32, 16B aligned rows (overlays X region)
#define SM_X   0                    // 128 * 400 = 51200
#define SM_B   51200                // 64 * 400 = 25600
#define SM_W2  76800                // [32][64] f32 = 8192
#define SM_W3  84992                // [16][32] f32 = 2048
#define SM_W4  87040                // 16 f32
#define SM_BC  87104                // 64 f32
#define SM_B2  87360                // 32 f32
#define SM_B3  87488                // 16 f32
#define SM_B4  87552                // 1 f32 + pad
#define SMEM_DYN 87568

// ---------------------------------------------------------------------------
__global__ void setup_kernel(const float* __restrict__ w_lin,
                             const float* __restrict__ b_lin,
                             const float* __restrict__ w1,
                             const float* __restrict__ b1,
                             const float* __restrict__ w2,
                             const float* __restrict__ w3,
                             const void*  lidar_raw)
{
    int idx = blockIdx.x * blockDim.x + threadIdx.x;
    if (idx == 0) {
        const int* w = (const int*)lidar_raw;
        int all0 = 1;
        for (int i = 0; i < 32; i++) all0 &= (w[2 * i + 1] == 0);
        g_coord64 = all0;
    }
    if (idx < 12288) {               // WcT[j][k] bf16
        int j = idx / 192, k = idx % 192;
        float s;
        if (k < 128) {
            s = 0.f;
            for (int m = 0; m < 64; m++) s = fmaf(w_lin[k * 64 + m], w1[m * 64 + j], s);
        } else {
            s = w1[(64 + (k - 128)) * 64 + j];
        }
        g_WcT[idx] = __float2bfloat16(s);
    } else if (idx < 12352) {        // bc
        int j = idx - 12288;
        float s = b1[j];
        for (int m = 0; m < 64; m++) s = fmaf(b_lin[m], w1[m * 64 + j], s);
        g_bc[j] = s;
    } else if (idx < 14400) {        // w2T
        int t = idx - 12352; int j = t / 64, k = t % 64;
        g_w2T[t] = w2[k * 32 + j];
    } else if (idx < 14912) {        // w3T
        int t = idx - 14400; int j = t / 32, k = t % 32;
        g_w3T[t] = w3[k * 16 + j];
    }
}

// ---------------------------------------------------------------------------
// Transpose (B,C,H,W) x3 fp32 maps -> bf16 scratch[b][hw][192ch]
// ---------------------------------------------------------------------------
__global__ void transpose_kernel(const float* __restrict__ p0,
                                 const float* __restrict__ p1,
                                 const float* __restrict__ fl)
{
    __shared__ float T[64][65];
    int b = blockIdx.y;
    size_t hw0 = (size_t)blockIdx.x * 64;
    const float* maps[3] = {p0, p1, fl};
#pragma unroll
    for (int m = 0; m < 3; m++) {
        const float* src = maps[m] + (size_t)b * CDIM * HWSZ;
        for (int i = threadIdx.x; i < 4096; i += 256) {
            int c = i >> 6, x = i & 63;
            T[c][x] = src[(size_t)c * HWSZ + hw0 + x];
        }
        __syncthreads();
        __nv_bfloat16* dst = g_scratch + ((size_t)b * HWSZ + hw0) * 192 + m * 64;
        for (int i = threadIdx.x; i < 2048; i += 256) {
            int y = i >> 5, c2 = i & 31;
            float2 f2 = make_float2(T[2 * c2][y], T[2 * c2 + 1][y]);
            *(__nv_bfloat162*)(dst + (size_t)y * 192 + 2 * c2) = __float22bfloat162_rn(f2);
        }
        __syncthreads();
    }
}

// ---------------------------------------------------------------------------
// Fused gather + HMMA layer1 + FFMA2 tail. 128 points/block, 128 threads.
// ---------------------------------------------------------------------------
__global__ __launch_bounds__(128, 2)
void mlp_kernel(const void* __restrict__ lc_raw, const void* __restrict__ rc_raw,
                const float* __restrict__ w4, const float* __restrict__ b2,
                const float* __restrict__ b3, const float* __restrict__ b4,
                float* __restrict__ out, int Nl, int Nr)
{
    extern __shared__ char sm[];
    uint32_t sbase = smem_u32(sm);

    int tid = threadIdx.x;
    int w = tid >> 5, lane = tid & 31;
    int b = blockIdx.y;
    int N = Nl + Nr;
    int pt0 = blockIdx.x * 128;

    // ---- stage weights ----
    for (int i = tid; i < 1536; i += 128) {      // WcT rows -> SM_B (400B pitch)
        int j = i / 24, g = i % 24;
        *(uint4*)(sm + SM_B + j * XPITCH + g * 16) = ((const uint4*)g_WcT)[j * 24 + g];
    }
    for (int i = tid; i < 2048; i += 128) ((float*)(sm + SM_W2))[i] = g_w2T[i];
    for (int i = tid; i < 512; i += 128)  ((float*)(sm + SM_W3))[i] = g_w3T[i];
    if (tid < 16) ((float*)(sm + SM_W4))[tid] = w4[tid];
    if (tid < 64) ((float*)(sm + SM_BC))[tid] = g_bc[tid];
    if (tid < 32) ((float*)(sm + SM_B2))[tid] = b2[tid];
    if (tid < 16) ((float*)(sm + SM_B3))[tid] = b3[tid];
    if (tid == 0) ((float*)(sm + SM_B4))[0] = b4[0];

    // ---- gather: one thread per point, 384B bf16 row -> X row (400B pitch) ----
    {
        int is64 = g_coord64;
        int pt = pt0 + tid;
        if (pt < N) {
            long long r, c;
            if (pt < Nl) {
                long long base = ((long long)b * Nl + pt) * 3;
                if (is64) { const long long* lc = (const long long*)lc_raw; r = lc[base + 1]; c = lc[base + 2]; }
                else      { const int*       lc = (const int*)lc_raw;       r = lc[base + 1]; c = lc[base + 2]; }
            } else {
                long long base = ((long long)b * Nr + (pt - Nl)) * 3;
                if (is64) { const long long* rc = (const long long*)rc_raw; r = rc[base + 1]; c = rc[base + 2]; }
                else      { const int*       rc = (const int*)rc_raw;       r = rc[base + 1]; c = rc[base + 2]; }
            }
            const uint4* rowptr = (const uint4*)(g_scratch +
                192ull * ((size_t)b * HWSZ + (size_t)r * WDIM + (size_t)c));
#pragma unroll
            for (int g = 0; g < 24; g++)
                *(uint4*)(sm + SM_X + tid * XPITCH + g * 16) = rowptr[g];
        } else {
#pragma unroll
            for (int g = 0; g < 24; g++)
                *(uint4*)(sm + SM_X + tid * XPITCH + g * 16) = make_uint4(0, 0, 0, 0);
        }
    }
    __syncthreads();

    // ---- layer 1: warp w computes points [w*32, w*32+32) x 64 outputs ----
    float D[2][8][4] = {};
    {
        uint32_t a_row = (lane & 7) + ((lane >> 3) & 1) * 8;
        uint32_t a_k   = ((lane >> 4) & 1) * 16;
        uint32_t aB0 = sbase + SM_X + (w * 32 + a_row) * XPITCH + a_k;
        uint32_t aB1 = aB0 + 16 * XPITCH;
        uint32_t b_row = lane & 7;
        uint32_t b_k   = ((lane >> 3) & 1) * 16;
        uint32_t bB  = sbase + SM_B + b_row * XPITCH + b_k;
#pragma unroll
        for (int kk = 0; kk < 12; kk++) {
            uint32_t a0[4], a1[4];
            ldsm4(a0, aB0 + kk * 32);
            ldsm4(a1, aB1 + kk * 32);
#pragma unroll
            for (int j = 0; j < 8; j++) {
                uint32_t bf[2];
                ldsm2(bf, bB + j * 8 * XPITCH + kk * 32);
                mma16816(D[0][j], a0, bf);
                mma16816(D[1][j], a1, bf);
            }
        }
    }
    __syncthreads();   // all ldmatrix reads of X done before H1 overlays it

    // ---- bias + gelu, store H1[128][68] f32 (overlays X region) ----
    {
        const float* bcs = (const float*)(sm + SM_BC);
        int g = lane >> 2, t = lane & 3;
#pragma unroll
        for (int mi = 0; mi < 2; mi++) {
            int p0r = w * 32 + mi * 16 + g;
#pragma unroll
            for (int j = 0; j < 8; j++) {
                int c0 = j * 8 + 2 * t;
                float b0v = bcs[c0], b1v = bcs[c0 + 1];
                *(float2*)(sm + p0r * HPITCH + c0 * 4) =
                    make_float2(gelu_exact(D[mi][j][0] + b0v), gelu_exact(D[mi][j][1] + b1v));
                *(float2*)(sm + (p0r + 8) * HPITCH + c0 * 4) =
                    make_float2(gelu_exact(D[mi][j][2] + b0v), gelu_exact(D[mi][j][3] + b1v));
            }
        }
    }
    __syncwarp();      // H1 rows for this warp's points written only by this warp

    // ---- layers 2-4 per thread (one point each), packed FFMA2 ----
    {
        unsigned long long hp[32];
        const ulonglong2* hrow = (const ulonglong2*)(sm + tid * HPITCH);
#pragma unroll
        for (int q = 0; q < 16; q++) { ulonglong2 v = hrow[q]; hp[2 * q] = v.x; hp[2 * q + 1] = v.y; }

        const float* b2s = (const float*)(sm + SM_B2);
        float h2[32];
#pragma unroll
        for (int j = 0; j < 32; j++) {
            const ulonglong2* wr = (const ulonglong2*)(sm + SM_W2 + j * 256);
            unsigned long long acc = 0;
#pragma unroll
            for (int q = 0; q < 16; q++) {          // 16 x ulonglong2 = 64 floats
                ulonglong2 wv = wr[q];
                acc = fma2(hp[2 * q], wv.x, acc);
                acc = fma2(hp[2 * q + 1], wv.y, acc);
            }
            float2 f = unpack2(acc);
            h2[j] = gelu_exact(f.x + f.y + b2s[j]);
        }
        unsigned long long hp2[16];
#pragma unroll
        for (int i = 0; i < 16; i++) hp2[i] = pack2(h2[2 * i], h2[2 * i + 1]);

        const float* b3s = (const float*)(sm + SM_B3);
        float h3[16];
#pragma unroll
        for (int j = 0; j < 16; j++) {
            const ulonglong2* wr = (const ulonglong2*)(sm + SM_W3 + j * 128);
            unsigned long long acc = 0;
#pragma unroll
            for (int q = 0; q < 8; q++) {           // 8 x ulonglong2 = 32 floats
                ulonglong2 wv = wr[q];
                acc = fma2(hp2[2 * q], wv.x, acc);
                acc = fma2(hp2[2 * q + 1], wv.y, acc);
            }
            float2 f = unpack2(acc);
            h3[j] = gelu_exact(f.x + f.y + b3s[j]);
        }
        {
            const ulonglong2* wr = (const ulonglong2*)(sm + SM_W4);
            unsigned long long acc = 0;
#pragma unroll
            for (int q = 0; q < 4; q++) {           // 4 x ulonglong2 = 16 floats
                ulonglong2 wv = wr[q];
                acc = fma2(pack2(h3[4 * q], h3[4 * q + 1]), wv.x, acc);
                acc = fma2(pack2(h3[4 * q + 2], h3[4 * q + 3]), wv.y, acc);
            }
            float2 f = unpack2(acc);
            float s = f.x + f.y + ((const float*)(sm + SM_B4))[0];
            int pt = pt0 + tid;
            if (pt < N) out[(size_t)b * N + pt] = 1.f / (1.f + expf(-s));
        }
    }
}

// ---------------------------------------------------------------------------
extern "C" void kernel_launch(void* const* d_in, const int* in_sizes, int n_in,
                              void* d_out, int out_size)
{
    const float* p0    = (const float*)d_in[0];
    const float* p1    = (const float*)d_in[1];
    const float* fl    = (const float*)d_in[2];
    const void*  lc    = d_in[3];
    const void*  rc    = d_in[4];
    const float* w_lin = (const float*)d_in[5];
    const float* b_lin = (const float*)d_in[6];
    const float* w1    = (const float*)d_in[7];
    const float* b1    = (const float*)d_in[8];
    const float* w2    = (const float*)d_in[9];
    const float* b2    = (const float*)d_in[10];
    const float* w3    = (const float*)d_in[11];
    const float* b3    = (const float*)d_in[12];
    const float* w4    = (const float*)d_in[13];
    const float* b4    = (const float*)d_in[14];

    int B  = in_sizes[0] / (CDIM * HWSZ);   // = 2
    int Nl = in_sizes[3] / (B * 3);
    int Nr = in_sizes[4] / (B * 3);
    int N  = Nl + Nr;

    setup_kernel<<<59, 256>>>(w_lin, b_lin, w1, b1, w2, w3, lc);

    dim3 tg(HWSZ / 64, B);
    transpose_kernel<<<tg, 256>>>(p0, p1, fl);

    cudaFuncSetAttribute(mlp_kernel, cudaFuncAttributeMaxDynamicSharedMemorySize, SMEM_DYN);
    dim3 mg((N + 127) / 128, B);
    mlp_kernel<<<mg, 128, SMEM_DYN>>>(lc, rc, w4, b2, b3, b4, (float*)d_out, Nl, Nr);
}